// round 10
// baseline (speedup 1.0000x reference)
#include <cuda_runtime.h>
#include <cuda_bf16.h>
#include <math_constants.h>
#include <cstdint>

// KCRouteEncoder:
//   out = pooled_cid + bias + (pooled_content @ W)     (alphas sum to 1)
// Round 10: position range split into 4 chunks; pool chunks on the capture
// stream, GEMM chunks on a second stream gated by events -> GEMM overlaps the
// (DRAM-bound) pool. GEMM smem now XOR-swizzled (conflict-free ldmatrix).

#define KLEV   8
#define EMB    256
#define PDIM   768
#define MAXPOS 12800

#define BM 32
#define BK 64
#define NCHUNK (PDIM / BK)                 // 12
#define A_STG_B 4096                       // 32 rows x 128B
#define W_STG_B 32768                      // 64 rows x 512B
#define STG_B   (A_STG_B + W_STG_B)        // 36864
#define SMEM_TOTAL (2 * STG_B)             // 73728

#define WCONV_BLOCKS (PDIM * EMB / 256)    // 768
#define NPC 4                              // position chunks

__device__ __nv_bfloat16 g_P[(size_t)MAXPOS * PDIM];
__device__ __nv_bfloat16 g_W[(size_t)PDIM * EMB];

__device__ __forceinline__ uint32_t smem_u32(const void* p) {
    return (uint32_t)__cvta_generic_to_shared(p);
}
__device__ __forceinline__ void cp_async16(uint32_t dst, const void* src) {
    asm volatile("cp.async.cg.shared.global [%0], [%1], 16;\n" :: "r"(dst), "l"(src));
}
__device__ __forceinline__ void cp_commit() {
    asm volatile("cp.async.commit_group;\n");
}
template <int N>
__device__ __forceinline__ void cp_wait() {
    asm volatile("cp.async.wait_group %0;\n" :: "n"(N));
}

// ------------------------------------------------ fallback W convert
__global__ void convert_w_kernel(const float* __restrict__ proj_w) {
    int i = blockIdx.x * blockDim.x + threadIdx.x;
    if (i < PDIM * EMB)
        g_W[i] = __float2bfloat16_rn(__ldg(&proj_w[i]));
}

// ------------------------------------------------ K1: pool (R5 body + chunk start)
__global__ void __launch_bounds__(256)
pool_kernel(const int* __restrict__ croutes,
            const float* __restrict__ cid_emb,
            const float* __restrict__ weight,
            const float* __restrict__ content_table,
            const float* __restrict__ proj_w,
            const float* __restrict__ proj_b,
            float* __restrict__ out,
            int start, int do_conv, int npos)
{
    const int pos = start + blockIdx.x;
    const int t   = threadIdx.x;

    if (do_conv && blockIdx.x < WCONV_BLOCKS) {
        int i = blockIdx.x * 256 + t;
        g_W[i] = __float2bfloat16_rn(__ldg(&proj_w[i]));
    }
    if (pos >= npos) return;

    __shared__ int   rels[KLEV];
    __shared__ float alph[KLEV];

    if (t < KLEV)
        rels[t] = croutes[(size_t)pos * KLEV + t] + 2;
    __syncthreads();

    if (t == 0) {
        float nw[KLEV];
        float m = -CUDART_INF_F;
#pragma unroll
        for (int k = 0; k < KLEV; k++) {
            nw[k] = (rels[k] != 0) ? __ldg(&weight[k]) : -CUDART_INF_F;
            m = fmaxf(m, nw[k]);
        }
        float s = 0.f, ex[KLEV];
#pragma unroll
        for (int k = 0; k < KLEV; k++) { ex[k] = expf(nw[k] - m); s += ex[k]; }
        float inv = 1.f / s;
#pragma unroll
        for (int k = 0; k < KLEV; k++) alph[k] = ex[k] * inv;
    }
    __syncthreads();

    float a[KLEV]; int r[KLEV];
#pragma unroll
    for (int k = 0; k < KLEV; k++) { a[k] = alph[k]; r[k] = rels[k]; }

    if (t < 192) {
        float4 s = make_float4(0.f, 0.f, 0.f, 0.f);
#pragma unroll
        for (int k = 0; k < KLEV; k++) {
            if (a[k] != 0.f) {
                float4 v = __ldg(((const float4*)content_table) + (size_t)r[k] * 192 + t);
                s.x = fmaf(a[k], v.x, s.x);
                s.y = fmaf(a[k], v.y, s.y);
                s.z = fmaf(a[k], v.z, s.z);
                s.w = fmaf(a[k], v.w, s.w);
            }
        }
        __nv_bfloat162 lo = __floats2bfloat162_rn(s.x, s.y);
        __nv_bfloat162 hi = __floats2bfloat162_rn(s.z, s.w);
        uint2 pk;
        pk.x = *reinterpret_cast<uint32_t*>(&lo);
        pk.y = *reinterpret_cast<uint32_t*>(&hi);
        *reinterpret_cast<uint2*>(g_P + (size_t)pos * PDIM + 4 * t) = pk;
    } else {
        int u = t - 192;
        float4 s = __ldg(((const float4*)proj_b) + u);
#pragma unroll
        for (int k = 0; k < KLEV; k++) {
            if (a[k] != 0.f && r[k] >= 2) {
                float4 v = __ldg(((const float4*)cid_emb) + (size_t)(r[k] - 2) * 64 + u);
                s.x = fmaf(a[k], v.x, s.x);
                s.y = fmaf(a[k], v.y, s.y);
                s.z = fmaf(a[k], v.z, s.z);
                s.w = fmaf(a[k], v.w, s.w);
            }
        }
        *reinterpret_cast<float4*>(out + (size_t)pos * EMB + 4 * u) = s;
    }
}

// ------------------------------------------------ K2: GEMM (XOR-swizzled smem)
// out[rows, 256] += g_P[rows, 768] @ g_W[768, 256]; rows = rowStart + bx*32 ...
__global__ void __launch_bounds__(256, 2)
gemm_kernel(float* __restrict__ out, int rowStart, int npos)
{
    extern __shared__ __align__(16) char smem[];

    const int t    = threadIdx.x;
    const int warp = t >> 5;
    const int lane = t & 31;
    const int blockRow = rowStart + blockIdx.x * BM;

    float c[2][4][4];
#pragma unroll
    for (int mf = 0; mf < 2; mf++)
#pragma unroll
        for (int nf = 0; nf < 4; nf++)
#pragma unroll
            for (int i = 0; i < 4; i++) c[mf][nf][i] = 0.f;

    // A: 32 rows x 8 chunks of 16B; one chunk per thread
    const int a_row = t >> 3, a_ch = t & 7;
    int grow = blockRow + a_row; if (grow >= npos) grow = npos - 1;
    const __nv_bfloat16* a_src_base = g_P + (size_t)grow * PDIM + a_ch * 8;
    const uint32_t a_dst_off = a_row * 128 + ((a_ch ^ (a_row & 7)) * 16);

    auto load_chunk = [&](int kc, int buf) {
        char* base = smem + buf * STG_B;
        cp_async16(smem_u32(base + a_dst_off), a_src_base + kc * BK);
        char* Wb = base + A_STG_B;
#pragma unroll
        for (int i = 0; i < 8; i++) {
            int u  = t + i * 256;             // 0..2047
            int wr = u >> 5, wc = u & 31;     // row 0..63, chunk 0..31
            cp_async16(smem_u32(Wb + wr * 512 + ((wc ^ (wr & 7)) * 16)),
                       g_W + (size_t)(kc * BK + wr) * EMB + wc * 8);
        }
        cp_commit();
    };

    load_chunk(0, 0);

    for (int kc = 0; kc < NCHUNK; kc++) {
        if (kc + 1 < NCHUNK) {
            load_chunk(kc + 1, (kc + 1) & 1);
            cp_wait<1>();
        } else {
            cp_wait<0>();
        }
        __syncthreads();

        const char* As = smem + (kc & 1) * STG_B;
        const char* Ws = As + A_STG_B;

#pragma unroll
        for (int ks = 0; ks < BK / 16; ks++) {
            uint32_t a[2][4];
#pragma unroll
            for (int mf = 0; mf < 2; mf++) {
                int row = mf * 16 + (lane & 15);
                int ch  = ks * 2 + (lane >> 4);
                uint32_t addr = smem_u32(As + row * 128 + ((ch ^ (row & 7)) * 16));
                asm volatile("ldmatrix.sync.aligned.m8n8.x4.shared.b16 {%0,%1,%2,%3}, [%4];\n"
                             : "=r"(a[mf][0]), "=r"(a[mf][1]), "=r"(a[mf][2]), "=r"(a[mf][3])
                             : "r"(addr));
            }
            uint32_t b[4][2];
#pragma unroll
            for (int nf = 0; nf < 4; nf++) {
                int row = ks * 16 + (lane & 15);
                int ch  = warp * 4 + nf;      // 16B chunk = 8 bf16 cols
                uint32_t addr = smem_u32(Ws + row * 512 + ((ch ^ (row & 7)) * 16));
                asm volatile("ldmatrix.sync.aligned.m8n8.x2.trans.shared.b16 {%0,%1}, [%2];\n"
                             : "=r"(b[nf][0]), "=r"(b[nf][1]) : "r"(addr));
            }
#pragma unroll
            for (int mf = 0; mf < 2; mf++)
#pragma unroll
                for (int nf = 0; nf < 4; nf++) {
                    asm volatile(
                        "mma.sync.aligned.m16n8k16.row.col.f32.bf16.bf16.f32 "
                        "{%0,%1,%2,%3}, {%4,%5,%6,%7}, {%8,%9}, {%0,%1,%2,%3};\n"
                        : "+f"(c[mf][nf][0]), "+f"(c[mf][nf][1]),
                          "+f"(c[mf][nf][2]), "+f"(c[mf][nf][3])
                        : "r"(a[mf][0]), "r"(a[mf][1]), "r"(a[mf][2]), "r"(a[mf][3]),
                          "r"(b[nf][0]), "r"(b[nf][1]));
                }
        }
        __syncthreads();
    }

    // epilogue: out += C
#pragma unroll
    for (int mf = 0; mf < 2; mf++) {
#pragma unroll
        for (int nf = 0; nf < 4; nf++) {
            int col = warp * 32 + nf * 8 + (lane & 3) * 2;
            int row0 = blockRow + mf * 16 + (lane >> 2);
            if (row0 < npos) {
                float2* o = reinterpret_cast<float2*>(&out[(size_t)row0 * EMB + col]);
                float2 v = *o;
                v.x += c[mf][nf][0]; v.y += c[mf][nf][1];
                *o = v;
            }
            int row1 = row0 + 8;
            if (row1 < npos) {
                float2* o = reinterpret_cast<float2*>(&out[(size_t)row1 * EMB + col]);
                float2 v = *o;
                v.x += c[mf][nf][2]; v.y += c[mf][nf][3];
                *o = v;
            }
        }
    }
}

// ------------------------------------------------ launch
extern "C" void kernel_launch(void* const* d_in, const int* in_sizes, int n_in,
                              void* d_out, int out_size)
{
    const int*   croutes       = (const int*)d_in[0];
    // d_in[1] = tailcs (unused)
    const float* cid_emb       = (const float*)d_in[2];
    const float* weight        = (const float*)d_in[3];
    const float* content_table = (const float*)d_in[4];
    const float* proj_w        = (const float*)d_in[5];
    const float* proj_b        = (const float*)d_in[6];
    float*       out           = (float*)d_out;

    int npos = in_sizes[0] / KLEV;
    if (npos > MAXPOS) npos = MAXPOS;

    static bool inited = false;
    static cudaStream_t s2;
    static cudaEvent_t evP[NPC], evG;
    if (!inited) {
        cudaFuncSetAttribute(gemm_kernel,
                             cudaFuncAttributeMaxDynamicSharedMemorySize,
                             SMEM_TOTAL);
        cudaStreamCreateWithFlags(&s2, cudaStreamNonBlocking);
        for (int i = 0; i < NPC; i++)
            cudaEventCreateWithFlags(&evP[i], cudaEventDisableTiming);
        cudaEventCreateWithFlags(&evG, cudaEventDisableTiming);
        inited = true;
    }

    // descending chunk boundaries (multiples of 32): ~32%, 60%, 84%, 100%
    int b[NPC + 1];
    b[0] = 0;
    b[1] = ((npos * 8 / 25) / 32) * 32;
    b[2] = ((npos * 3 / 5) / 32) * 32;
    b[3] = ((npos * 21 / 25) / 32) * 32;
    b[4] = npos;
    for (int i = 1; i <= NPC; i++)          // enforce monotonicity for tiny npos
        if (b[i] < b[i - 1]) b[i] = b[i - 1];

    if (b[1] < WCONV_BLOCKS)                // fold needs >=768 blocks in chunk 0
        convert_w_kernel<<<(PDIM * EMB + 255) / 256, 256>>>(proj_w);

    // pool chunks on the capture (default) stream, each followed by an event
    for (int i = 0; i < NPC; i++) {
        int cnt = b[i + 1] - b[i];
        if (cnt > 0)
            pool_kernel<<<cnt, 256>>>(croutes, cid_emb, weight, content_table,
                                      proj_w, proj_b, out,
                                      b[i], (i == 0) ? 1 : 0, npos);
        cudaEventRecord(evP[i], 0);
    }

    // gemm chunks on stream 2, each gated by its pool chunk's event
    for (int i = 0; i < NPC; i++) {
        cudaStreamWaitEvent(s2, evP[i], 0);
        int cnt = b[i + 1] - b[i];
        if (cnt > 0) {
            int nblk = (cnt + BM - 1) / BM;
            gemm_kernel<<<nblk, 256, SMEM_TOTAL, s2>>>(out, b[i], npos);
        }
    }

    // join back to the default stream
    cudaEventRecord(evG, s2);
    cudaStreamWaitEvent(0, evG, 0);
}

// round 11
// speedup vs baseline: 1.2546x; 1.2546x over previous
#include <cuda_runtime.h>
#include <cuda_bf16.h>
#include <math_constants.h>
#include <cstdint>

// KCRouteEncoder:
//   out = pooled_cid + bias + (pooled_content @ W)     (alphas sum to 1)
// Serialized (overlap measured harmful 3x): pool -> gemm.
// K1 pool (R5 best, W-convert folded into first 768 blocks).
// K2 gemm: BM=32 x BN=256 x BK=64, 2-stage, XOR-swizzled smem (conflict-free
//     ldmatrix), 3 CTAs/SM.

#define KLEV   8
#define EMB    256
#define PDIM   768
#define MAXPOS 12800

#define BM 32
#define BK 64
#define NCHUNK (PDIM / BK)                 // 12
#define A_STG_B 4096                       // 32 rows x 128B
#define W_STG_B 32768                      // 64 rows x 512B
#define STG_B   (A_STG_B + W_STG_B)        // 36864
#define SMEM_TOTAL (2 * STG_B)             // 73728 -> 3 CTAs/SM

#define WCONV_BLOCKS (PDIM * EMB / 256)    // 768

__device__ __nv_bfloat16 g_P[(size_t)MAXPOS * PDIM];
__device__ __nv_bfloat16 g_W[(size_t)PDIM * EMB];

__device__ __forceinline__ uint32_t smem_u32(const void* p) {
    return (uint32_t)__cvta_generic_to_shared(p);
}
__device__ __forceinline__ void cp_async16(uint32_t dst, const void* src) {
    asm volatile("cp.async.cg.shared.global [%0], [%1], 16;\n" :: "r"(dst), "l"(src));
}
__device__ __forceinline__ void cp_commit() {
    asm volatile("cp.async.commit_group;\n");
}
template <int N>
__device__ __forceinline__ void cp_wait() {
    asm volatile("cp.async.wait_group %0;\n" :: "n"(N));
}

// ------------------------------------------------ fallback W convert (npos<768 only)
__global__ void convert_w_kernel(const float* __restrict__ proj_w) {
    int i = blockIdx.x * blockDim.x + threadIdx.x;
    if (i < PDIM * EMB)
        g_W[i] = __float2bfloat16_rn(__ldg(&proj_w[i]));
}

// ------------------------------------------------ K1: pool (identical to R5)
__global__ void __launch_bounds__(256)
pool_kernel(const int* __restrict__ croutes,
            const float* __restrict__ cid_emb,
            const float* __restrict__ weight,
            const float* __restrict__ content_table,
            const float* __restrict__ proj_w,
            const float* __restrict__ proj_b,
            float* __restrict__ out,
            int npos)
{
    const int pos = blockIdx.x;
    const int t   = threadIdx.x;

    if (blockIdx.x < WCONV_BLOCKS) {
        int i = blockIdx.x * 256 + t;
        g_W[i] = __float2bfloat16_rn(__ldg(&proj_w[i]));
    }
    if (pos >= npos) return;

    __shared__ int   rels[KLEV];
    __shared__ float alph[KLEV];

    if (t < KLEV)
        rels[t] = croutes[(size_t)pos * KLEV + t] + 2;
    __syncthreads();

    if (t == 0) {
        float nw[KLEV];
        float m = -CUDART_INF_F;
#pragma unroll
        for (int k = 0; k < KLEV; k++) {
            nw[k] = (rels[k] != 0) ? __ldg(&weight[k]) : -CUDART_INF_F;
            m = fmaxf(m, nw[k]);
        }
        float s = 0.f, ex[KLEV];
#pragma unroll
        for (int k = 0; k < KLEV; k++) { ex[k] = expf(nw[k] - m); s += ex[k]; }
        float inv = 1.f / s;
#pragma unroll
        for (int k = 0; k < KLEV; k++) alph[k] = ex[k] * inv;
    }
    __syncthreads();

    float a[KLEV]; int r[KLEV];
#pragma unroll
    for (int k = 0; k < KLEV; k++) { a[k] = alph[k]; r[k] = rels[k]; }

    if (t < 192) {
        float4 s = make_float4(0.f, 0.f, 0.f, 0.f);
#pragma unroll
        for (int k = 0; k < KLEV; k++) {
            if (a[k] != 0.f) {
                float4 v = __ldg(((const float4*)content_table) + (size_t)r[k] * 192 + t);
                s.x = fmaf(a[k], v.x, s.x);
                s.y = fmaf(a[k], v.y, s.y);
                s.z = fmaf(a[k], v.z, s.z);
                s.w = fmaf(a[k], v.w, s.w);
            }
        }
        __nv_bfloat162 lo = __floats2bfloat162_rn(s.x, s.y);
        __nv_bfloat162 hi = __floats2bfloat162_rn(s.z, s.w);
        uint2 pk;
        pk.x = *reinterpret_cast<uint32_t*>(&lo);
        pk.y = *reinterpret_cast<uint32_t*>(&hi);
        *reinterpret_cast<uint2*>(g_P + (size_t)pos * PDIM + 4 * t) = pk;
    } else {
        int u = t - 192;
        float4 s = __ldg(((const float4*)proj_b) + u);
#pragma unroll
        for (int k = 0; k < KLEV; k++) {
            if (a[k] != 0.f && r[k] >= 2) {
                float4 v = __ldg(((const float4*)cid_emb) + (size_t)(r[k] - 2) * 64 + u);
                s.x = fmaf(a[k], v.x, s.x);
                s.y = fmaf(a[k], v.y, s.y);
                s.z = fmaf(a[k], v.z, s.z);
                s.w = fmaf(a[k], v.w, s.w);
            }
        }
        *reinterpret_cast<float4*>(out + (size_t)pos * EMB + 4 * u) = s;
    }
}

// ------------------------------------------------ K2: GEMM (XOR-swizzled, 3 CTA/SM)
// out[M,256] += g_P[M,768] @ g_W[768,256]; 8 warps, warp w -> cols [32w,32w+32)
__global__ void __launch_bounds__(256, 3)
gemm_kernel(float* __restrict__ out, int npos)
{
    extern __shared__ __align__(16) char smem[];

    const int t    = threadIdx.x;
    const int warp = t >> 5;
    const int lane = t & 31;
    const int blockRow = blockIdx.x * BM;

    float c[2][4][4];
#pragma unroll
    for (int mf = 0; mf < 2; mf++)
#pragma unroll
        for (int nf = 0; nf < 4; nf++)
#pragma unroll
            for (int i = 0; i < 4; i++) c[mf][nf][i] = 0.f;

    // A: 32 rows x 8 chunks of 16B; one chunk per thread
    const int a_row = t >> 3, a_ch = t & 7;
    int grow = blockRow + a_row; if (grow >= npos) grow = npos - 1;
    const __nv_bfloat16* a_src_base = g_P + (size_t)grow * PDIM + a_ch * 8;
    const uint32_t a_dst_off = a_row * 128 + ((a_ch ^ (a_row & 7)) * 16);

    auto load_chunk = [&](int kc, int buf) {
        char* base = smem + buf * STG_B;
        cp_async16(smem_u32(base + a_dst_off), a_src_base + kc * BK);
        char* Wb = base + A_STG_B;
#pragma unroll
        for (int i = 0; i < 8; i++) {
            int u  = t + i * 256;             // 0..2047
            int wr = u >> 5, wc = u & 31;     // row 0..63, chunk 0..31
            cp_async16(smem_u32(Wb + wr * 512 + ((wc ^ (wr & 7)) * 16)),
                       g_W + (size_t)(kc * BK + wr) * EMB + wc * 8);
        }
        cp_commit();
    };

    load_chunk(0, 0);

    for (int kc = 0; kc < NCHUNK; kc++) {
        if (kc + 1 < NCHUNK) {
            load_chunk(kc + 1, (kc + 1) & 1);
            cp_wait<1>();
        } else {
            cp_wait<0>();
        }
        __syncthreads();

        const char* As = smem + (kc & 1) * STG_B;
        const char* Ws = As + A_STG_B;

#pragma unroll
        for (int ks = 0; ks < BK / 16; ks++) {
            uint32_t a[2][4];
#pragma unroll
            for (int mf = 0; mf < 2; mf++) {
                int row = mf * 16 + (lane & 15);
                int ch  = ks * 2 + (lane >> 4);
                uint32_t addr = smem_u32(As + row * 128 + ((ch ^ (row & 7)) * 16));
                asm volatile("ldmatrix.sync.aligned.m8n8.x4.shared.b16 {%0,%1,%2,%3}, [%4];\n"
                             : "=r"(a[mf][0]), "=r"(a[mf][1]), "=r"(a[mf][2]), "=r"(a[mf][3])
                             : "r"(addr));
            }
            uint32_t b[4][2];
#pragma unroll
            for (int nf = 0; nf < 4; nf++) {
                int row = ks * 16 + (lane & 15);
                int ch  = warp * 4 + nf;      // 16B chunk = 8 bf16 cols
                uint32_t addr = smem_u32(Ws + row * 512 + ((ch ^ (row & 7)) * 16));
                asm volatile("ldmatrix.sync.aligned.m8n8.x2.trans.shared.b16 {%0,%1}, [%2];\n"
                             : "=r"(b[nf][0]), "=r"(b[nf][1]) : "r"(addr));
            }
#pragma unroll
            for (int mf = 0; mf < 2; mf++)
#pragma unroll
                for (int nf = 0; nf < 4; nf++) {
                    asm volatile(
                        "mma.sync.aligned.m16n8k16.row.col.f32.bf16.bf16.f32 "
                        "{%0,%1,%2,%3}, {%4,%5,%6,%7}, {%8,%9}, {%0,%1,%2,%3};\n"
                        : "+f"(c[mf][nf][0]), "+f"(c[mf][nf][1]),
                          "+f"(c[mf][nf][2]), "+f"(c[mf][nf][3])
                        : "r"(a[mf][0]), "r"(a[mf][1]), "r"(a[mf][2]), "r"(a[mf][3]),
                          "r"(b[nf][0]), "r"(b[nf][1]));
                }
        }
        __syncthreads();
    }

    // epilogue: out += C
#pragma unroll
    for (int mf = 0; mf < 2; mf++) {
#pragma unroll
        for (int nf = 0; nf < 4; nf++) {
            int col = warp * 32 + nf * 8 + (lane & 3) * 2;
            int row0 = blockRow + mf * 16 + (lane >> 2);
            if (row0 < npos) {
                float2* o = reinterpret_cast<float2*>(&out[(size_t)row0 * EMB + col]);
                float2 v = *o;
                v.x += c[mf][nf][0]; v.y += c[mf][nf][1];
                *o = v;
            }
            int row1 = row0 + 8;
            if (row1 < npos) {
                float2* o = reinterpret_cast<float2*>(&out[(size_t)row1 * EMB + col]);
                float2 v = *o;
                v.x += c[mf][nf][2]; v.y += c[mf][nf][3];
                *o = v;
            }
        }
    }
}

// ------------------------------------------------ launch
extern "C" void kernel_launch(void* const* d_in, const int* in_sizes, int n_in,
                              void* d_out, int out_size)
{
    const int*   croutes       = (const int*)d_in[0];
    // d_in[1] = tailcs (unused)
    const float* cid_emb       = (const float*)d_in[2];
    const float* weight        = (const float*)d_in[3];
    const float* content_table = (const float*)d_in[4];
    const float* proj_w        = (const float*)d_in[5];
    const float* proj_b        = (const float*)d_in[6];
    float*       out           = (float*)d_out;

    int npos = in_sizes[0] / KLEV;
    if (npos > MAXPOS) npos = MAXPOS;

    if (npos < WCONV_BLOCKS)
        convert_w_kernel<<<(PDIM * EMB + 255) / 256, 256>>>(proj_w);

    pool_kernel<<<npos, 256>>>(croutes, cid_emb, weight, content_table,
                               proj_w, proj_b, out, npos);

    static bool attr_set = false;
    if (!attr_set) {
        cudaFuncSetAttribute(gemm_kernel,
                             cudaFuncAttributeMaxDynamicSharedMemorySize,
                             SMEM_TOTAL);
        attr_set = true;
    }
    gemm_kernel<<<(npos + BM - 1) / BM, 256, SMEM_TOTAL>>>(out, npos);
}

// round 12
// speedup vs baseline: 1.2737x; 1.0152x over previous
#include <cuda_runtime.h>
#include <cuda_bf16.h>
#include <math_constants.h>
#include <cstdint>

// KCRouteEncoder:
//   out = pooled_cid + bias + (pooled_content @ W)     (alphas sum to 1)
// Serialized pool -> gemm (overlap measured harmful 3x).
// K1 pool (R5 best, W-convert folded into first 768 blocks).
// K2 gemm v7: BM=64 x BN=128 x BK=64, XOR-swizzled smem, 3-stage cp.async,
//     3 CTAs/SM, grid (ceil(npos/64), 2) = 400 blocks (~0.9 waves).

#define KLEV   8
#define EMB    256
#define PDIM   768
#define MAXPOS 12800

#define BM 64
#define BN 128
#define BK 64
#define NCHUNK (PDIM / BK)                 // 12
#define NSTAGE 3
#define A_STG_B (BM * 128)                 // 8192  (64 rows x 128B)
#define W_STG_B (BK * 256)                 // 16384 (64 rows x 256B)
#define STG_B   (A_STG_B + W_STG_B)        // 24576
#define SMEM_TOTAL (NSTAGE * STG_B)        // 73728 -> 3 CTAs/SM

#define WCONV_BLOCKS (PDIM * EMB / 256)    // 768

__device__ __nv_bfloat16 g_P[(size_t)MAXPOS * PDIM];
__device__ __nv_bfloat16 g_W[(size_t)PDIM * EMB];

__device__ __forceinline__ uint32_t smem_u32(const void* p) {
    return (uint32_t)__cvta_generic_to_shared(p);
}
__device__ __forceinline__ void cp_async16(uint32_t dst, const void* src) {
    asm volatile("cp.async.cg.shared.global [%0], [%1], 16;\n" :: "r"(dst), "l"(src));
}
__device__ __forceinline__ void cp_commit() {
    asm volatile("cp.async.commit_group;\n");
}
template <int N>
__device__ __forceinline__ void cp_wait() {
    asm volatile("cp.async.wait_group %0;\n" :: "n"(N));
}

// ------------------------------------------------ fallback W convert (npos<768 only)
__global__ void convert_w_kernel(const float* __restrict__ proj_w) {
    int i = blockIdx.x * blockDim.x + threadIdx.x;
    if (i < PDIM * EMB)
        g_W[i] = __float2bfloat16_rn(__ldg(&proj_w[i]));
}

// ------------------------------------------------ K1: pool (identical to R5/R11)
__global__ void __launch_bounds__(256)
pool_kernel(const int* __restrict__ croutes,
            const float* __restrict__ cid_emb,
            const float* __restrict__ weight,
            const float* __restrict__ content_table,
            const float* __restrict__ proj_w,
            const float* __restrict__ proj_b,
            float* __restrict__ out,
            int npos)
{
    const int pos = blockIdx.x;
    const int t   = threadIdx.x;

    if (blockIdx.x < WCONV_BLOCKS) {
        int i = blockIdx.x * 256 + t;
        g_W[i] = __float2bfloat16_rn(__ldg(&proj_w[i]));
    }
    if (pos >= npos) return;

    __shared__ int   rels[KLEV];
    __shared__ float alph[KLEV];

    if (t < KLEV)
        rels[t] = croutes[(size_t)pos * KLEV + t] + 2;
    __syncthreads();

    if (t == 0) {
        float nw[KLEV];
        float m = -CUDART_INF_F;
#pragma unroll
        for (int k = 0; k < KLEV; k++) {
            nw[k] = (rels[k] != 0) ? __ldg(&weight[k]) : -CUDART_INF_F;
            m = fmaxf(m, nw[k]);
        }
        float s = 0.f, ex[KLEV];
#pragma unroll
        for (int k = 0; k < KLEV; k++) { ex[k] = expf(nw[k] - m); s += ex[k]; }
        float inv = 1.f / s;
#pragma unroll
        for (int k = 0; k < KLEV; k++) alph[k] = ex[k] * inv;
    }
    __syncthreads();

    float a[KLEV]; int r[KLEV];
#pragma unroll
    for (int k = 0; k < KLEV; k++) { a[k] = alph[k]; r[k] = rels[k]; }

    if (t < 192) {
        float4 s = make_float4(0.f, 0.f, 0.f, 0.f);
#pragma unroll
        for (int k = 0; k < KLEV; k++) {
            if (a[k] != 0.f) {
                float4 v = __ldg(((const float4*)content_table) + (size_t)r[k] * 192 + t);
                s.x = fmaf(a[k], v.x, s.x);
                s.y = fmaf(a[k], v.y, s.y);
                s.z = fmaf(a[k], v.z, s.z);
                s.w = fmaf(a[k], v.w, s.w);
            }
        }
        __nv_bfloat162 lo = __floats2bfloat162_rn(s.x, s.y);
        __nv_bfloat162 hi = __floats2bfloat162_rn(s.z, s.w);
        uint2 pk;
        pk.x = *reinterpret_cast<uint32_t*>(&lo);
        pk.y = *reinterpret_cast<uint32_t*>(&hi);
        *reinterpret_cast<uint2*>(g_P + (size_t)pos * PDIM + 4 * t) = pk;
    } else {
        int u = t - 192;
        float4 s = __ldg(((const float4*)proj_b) + u);
#pragma unroll
        for (int k = 0; k < KLEV; k++) {
            if (a[k] != 0.f && r[k] >= 2) {
                float4 v = __ldg(((const float4*)cid_emb) + (size_t)(r[k] - 2) * 64 + u);
                s.x = fmaf(a[k], v.x, s.x);
                s.y = fmaf(a[k], v.y, s.y);
                s.z = fmaf(a[k], v.z, s.z);
                s.w = fmaf(a[k], v.w, s.w);
            }
        }
        *reinterpret_cast<float4*>(out + (size_t)pos * EMB + 4 * u) = s;
    }
}

// ------------------------------------------------ K2: GEMM v7
// block (bx, by): rows [64bx,64bx+64), cols [128by, 128by+128)
// 8 warps = 2(M) x 4(N): wm = warp&1 (32 rows), wn = warp>>1 (32 cols)
__global__ void __launch_bounds__(256, 3)
gemm_kernel(float* __restrict__ out, int npos)
{
    extern __shared__ __align__(16) char smem[];

    const int t    = threadIdx.x;
    const int warp = t >> 5;
    const int lane = t & 31;
    const int wm   = warp & 1;
    const int wn   = warp >> 1;
    const int blockRow = blockIdx.x * BM;
    const int nbase    = blockIdx.y * BN;

    float c[2][4][4];
#pragma unroll
    for (int mf = 0; mf < 2; mf++)
#pragma unroll
        for (int nf = 0; nf < 4; nf++)
#pragma unroll
            for (int i = 0; i < 4; i++) c[mf][nf][i] = 0.f;

    // A: 64 rows x 8 chunks of 16B = 512; 2 per thread (u = t, t+256)
    const int a_row0 = t >> 3,         a_ch0 = t & 7;
    const int a_row1 = (t + 256) >> 3, a_ch1 = t & 7;
    int gr0 = blockRow + a_row0; if (gr0 >= npos) gr0 = npos - 1;
    int gr1 = blockRow + a_row1; if (gr1 >= npos) gr1 = npos - 1;
    const __nv_bfloat16* a_src0 = g_P + (size_t)gr0 * PDIM + a_ch0 * 8;
    const __nv_bfloat16* a_src1 = g_P + (size_t)gr1 * PDIM + a_ch1 * 8;
    const uint32_t a_off0 = a_row0 * 128 + ((a_ch0 ^ (a_row0 & 7)) * 16);
    const uint32_t a_off1 = a_row1 * 128 + ((a_ch1 ^ (a_row1 & 7)) * 16);

    auto load_chunk = [&](int kc, int stg) {
        char* base = smem + stg * STG_B;
        cp_async16(smem_u32(base + a_off0), a_src0 + kc * BK);
        cp_async16(smem_u32(base + a_off1), a_src1 + kc * BK);
        char* Wb = base + A_STG_B;
        // W: 64 rows x 16 chunks of 16B = 1024; 4 per thread
#pragma unroll
        for (int i = 0; i < 4; i++) {
            int u  = t + i * 256;             // 0..1023
            int wr = u >> 4, wc = u & 15;     // row 0..63, chunk 0..15
            cp_async16(smem_u32(Wb + wr * 256 + ((wc ^ (wr & 7)) * 16)),
                       g_W + (size_t)(kc * BK + wr) * EMB + nbase + wc * 8);
        }
        cp_commit();
    };

    load_chunk(0, 0);
    load_chunk(1, 1);
    load_chunk(2, 2);

    int stg = 0;
    for (int kc = 0; kc < NCHUNK; kc++) {
        // outstanding: chunks kc .. min(kc+2, NCHUNK-1)
        if (kc + 2 < NCHUNK)      cp_wait<2>();
        else if (kc + 1 < NCHUNK) cp_wait<1>();
        else                      cp_wait<0>();
        __syncthreads();

        const char* As = smem + stg * STG_B;
        const char* Ws = As + A_STG_B;

#pragma unroll
        for (int ks = 0; ks < BK / 16; ks++) {
            uint32_t a[2][4];
#pragma unroll
            for (int mf = 0; mf < 2; mf++) {
                int row = wm * 32 + mf * 16 + (lane & 15);
                int ch  = ks * 2 + (lane >> 4);
                uint32_t addr = smem_u32(As + row * 128 + ((ch ^ (row & 7)) * 16));
                asm volatile("ldmatrix.sync.aligned.m8n8.x4.shared.b16 {%0,%1,%2,%3}, [%4];\n"
                             : "=r"(a[mf][0]), "=r"(a[mf][1]), "=r"(a[mf][2]), "=r"(a[mf][3])
                             : "r"(addr));
            }
            uint32_t b[4][2];
#pragma unroll
            for (int nf = 0; nf < 4; nf++) {
                int row = ks * 16 + (lane & 15);
                int ch  = wn * 4 + nf;        // 16B chunk = 8 bf16 cols
                uint32_t addr = smem_u32(Ws + row * 256 + ((ch ^ (row & 7)) * 16));
                asm volatile("ldmatrix.sync.aligned.m8n8.x2.trans.shared.b16 {%0,%1}, [%2];\n"
                             : "=r"(b[nf][0]), "=r"(b[nf][1]) : "r"(addr));
            }
#pragma unroll
            for (int mf = 0; mf < 2; mf++)
#pragma unroll
                for (int nf = 0; nf < 4; nf++) {
                    asm volatile(
                        "mma.sync.aligned.m16n8k16.row.col.f32.bf16.bf16.f32 "
                        "{%0,%1,%2,%3}, {%4,%5,%6,%7}, {%8,%9}, {%0,%1,%2,%3};\n"
                        : "+f"(c[mf][nf][0]), "+f"(c[mf][nf][1]),
                          "+f"(c[mf][nf][2]), "+f"(c[mf][nf][3])
                        : "r"(a[mf][0]), "r"(a[mf][1]), "r"(a[mf][2]), "r"(a[mf][3]),
                          "r"(b[nf][0]), "r"(b[nf][1]));
                }
        }
        __syncthreads();

        if (kc + NSTAGE < NCHUNK) load_chunk(kc + NSTAGE, stg);
        stg = (stg == NSTAGE - 1) ? 0 : stg + 1;
    }

    // epilogue: out += C
#pragma unroll
    for (int mf = 0; mf < 2; mf++) {
#pragma unroll
        for (int nf = 0; nf < 4; nf++) {
            int col  = nbase + wn * 32 + nf * 8 + (lane & 3) * 2;
            int row0 = blockRow + wm * 32 + mf * 16 + (lane >> 2);
            if (row0 < npos) {
                float2* o = reinterpret_cast<float2*>(&out[(size_t)row0 * EMB + col]);
                float2 v = *o;
                v.x += c[mf][nf][0]; v.y += c[mf][nf][1];
                *o = v;
            }
            int row1 = row0 + 8;
            if (row1 < npos) {
                float2* o = reinterpret_cast<float2*>(&out[(size_t)row1 * EMB + col]);
                float2 v = *o;
                v.x += c[mf][nf][2]; v.y += c[mf][nf][3];
                *o = v;
            }
        }
    }
}

// ------------------------------------------------ launch
extern "C" void kernel_launch(void* const* d_in, const int* in_sizes, int n_in,
                              void* d_out, int out_size)
{
    const int*   croutes       = (const int*)d_in[0];
    // d_in[1] = tailcs (unused)
    const float* cid_emb       = (const float*)d_in[2];
    const float* weight        = (const float*)d_in[3];
    const float* content_table = (const float*)d_in[4];
    const float* proj_w        = (const float*)d_in[5];
    const float* proj_b        = (const float*)d_in[6];
    float*       out           = (float*)d_out;

    int npos = in_sizes[0] / KLEV;
    if (npos > MAXPOS) npos = MAXPOS;

    if (npos < WCONV_BLOCKS)
        convert_w_kernel<<<(PDIM * EMB + 255) / 256, 256>>>(proj_w);

    pool_kernel<<<npos, 256>>>(croutes, cid_emb, weight, content_table,
                               proj_w, proj_b, out, npos);

    static bool attr_set = false;
    if (!attr_set) {
        cudaFuncSetAttribute(gemm_kernel,
                             cudaFuncAttributeMaxDynamicSharedMemorySize,
                             SMEM_TOTAL);
        attr_set = true;
    }
    dim3 grid((npos + BM - 1) / BM, 2);
    gemm_kernel<<<grid, 256, SMEM_TOTAL>>>(out, npos);
}